// round 11
// baseline (speedup 1.0000x reference)
#include <cuda_runtime.h>
#include <math.h>

#define BB 4
#define NN 2048
#define MM 2048

// ---- persistent scratch (device globals; no allocation allowed) ----
__device__ __align__(16) float g_d2[BB * NN * MM];   // 64 MB squared distances (L2-resident)
__device__ float g_cmin[BB * NN * 16];               // per-row 128-col chunk minima
__device__ float g_remainL[BB * NN];
__device__ float g_remainR[BB * MM];
__device__ float g_ratioL[BB * NN];
__device__ float g_colA[BB * MM];   // colsum of w0*ratioL (for ratioR)
__device__ float g_colB[BB * MM];   // colsum of w (for remainR update)
__device__ float g_cost[BB];
__device__ int   g_sync = 0;        // kB completion counter (reset by last block)

__device__ __forceinline__ float ex2a(float x) {
    float y; asm("ex2.approx.f32 %0, %1;" : "=f"(y) : "f"(x)); return y;
}
__device__ __forceinline__ float sqrta(float x) {
    float y; asm("sqrt.approx.f32 %0, %1;" : "=f"(y) : "f"(x)); return y;
}

// ---- d2 (literal fp32 rounding) + chunk minima + state init
__global__ void k_d2(const float* __restrict__ tm, const float* __restrict__ sr) {
    __shared__ alignas(16) float sx[MM];
    __shared__ alignas(16) float sy[MM];
    __shared__ alignas(16) float sz[MM];
    int b = blockIdx.y;
    const float* sb = sr + (size_t)b * MM * 3;
    for (int i = threadIdx.x; i < MM; i += blockDim.x) {
        sx[i] = sb[3 * i]; sy[i] = sb[3 * i + 1]; sz[i] = sb[3 * i + 2];
    }
    if (blockIdx.x == 0) {       // fold k_init: one block per batch initializes state
        int bo = b * MM;
        for (int i = threadIdx.x; i < MM; i += blockDim.x) {
            g_remainL[b * NN + i] = 1.0f;   // multiL = 1 (N == M)
            g_remainR[bo + i] = 1.0f;
            g_colA[bo + i] = 0.0f;
            g_colB[bo + i] = 0.0f;
        }
        if (threadIdx.x == 0) g_cost[b] = 0.0f;
    }
    __syncthreads();
    int warp = threadIdx.x >> 5, lane = threadIdx.x & 31;
    int n = blockIdx.x * 8 + warp;
    size_t row = (size_t)(b * NN + n);
    const float* tp = tm + row * 3;
    float tx = tp[0], ty = tp[1], tz = tp[2];
    float* drow = g_d2 + row * MM;
#pragma unroll 2
    for (int it = 0; it < 16; ++it) {
        int m = it * 128 + lane * 4;
        float4 X = *(const float4*)(sx + m);
        float4 Y = *(const float4*)(sy + m);
        float4 Z = *(const float4*)(sz + m);
        float4 o;
        { float dx = __fadd_rn(tx, -X.x), dy = __fadd_rn(ty, -Y.x), dz = __fadd_rn(tz, -Z.x);
          o.x = __fadd_rn(__fadd_rn(__fmul_rn(dx, dx), __fmul_rn(dy, dy)), __fmul_rn(dz, dz)); }
        { float dx = __fadd_rn(tx, -X.y), dy = __fadd_rn(ty, -Y.y), dz = __fadd_rn(tz, -Z.y);
          o.y = __fadd_rn(__fadd_rn(__fmul_rn(dx, dx), __fmul_rn(dy, dy)), __fmul_rn(dz, dz)); }
        { float dx = __fadd_rn(tx, -X.z), dy = __fadd_rn(ty, -Y.z), dz = __fadd_rn(tz, -Z.z);
          o.z = __fadd_rn(__fadd_rn(__fmul_rn(dx, dx), __fmul_rn(dy, dy)), __fmul_rn(dz, dz)); }
        { float dx = __fadd_rn(tx, -X.w), dy = __fadd_rn(ty, -Y.w), dz = __fadd_rn(tz, -Z.w);
          o.w = __fadd_rn(__fadd_rn(__fmul_rn(dx, dx), __fmul_rn(dy, dy)), __fmul_rn(dz, dz)); }
        *(float4*)(drow + m) = o;
        float mn = fminf(fminf(o.x, o.y), fminf(o.z, o.w));
#pragma unroll
        for (int s = 16; s; s >>= 1) mn = fminf(mn, __shfl_xor_sync(0xffffffffu, mn, s));
        if (lane == 0) g_cmin[row * 16 + it] = mn;
    }
}

// --------------------------------------------------------------- kA
// 8 rows/block (grid 1024). Phase 1: suml -> ratioL (1 row/warp).
// Phase 2 (column-ownership, float4): colA[c] += sum_rows w0*ratioL.
// Chunk skip: rn(kl2*cmin) <= -126 (log2 units) => all 128 ex2 flush to 0.
__global__ void __launch_bounds__(256, 5) kA(float kl2) {   // kl2 = level*log2(e)
    __shared__ float s_rl[8];
    __shared__ float s_cm[8 * 16];            // cmin cache for the block's rows
    int b = blockIdx.y;
    int row0 = blockIdx.x * 8;
    if (threadIdx.x < 128)
        s_cm[threadIdx.x] = g_cmin[(size_t)(b * NN + row0) * 16 + threadIdx.x];
    __syncthreads();
    int warp = threadIdx.x >> 5, lane = threadIdx.x & 31;
    // ---- phase 1: one row per warp
    {
        size_t row = (size_t)(b * NN + row0 + warp);
        const float* drow = g_d2 + row * MM;
        const float* rmg = g_remainR + b * MM;
        float suml = 0.0f;
#pragma unroll 2
        for (int it = 0; it < 16; ++it) {
            if (__fmul_rn(kl2, s_cm[warp * 16 + it]) > -126.0f) {
                int m = it * 128 + lane * 4;
                float4 d4 = *(const float4*)(drow + m);
                float4 rm = __ldg((const float4*)(rmg + m));
                suml = fmaf(ex2a(__fmul_rn(kl2, d4.x)), rm.x, suml);
                suml = fmaf(ex2a(__fmul_rn(kl2, d4.y)), rm.y, suml);
                suml = fmaf(ex2a(__fmul_rn(kl2, d4.z)), rm.z, suml);
                suml = fmaf(ex2a(__fmul_rn(kl2, d4.w)), rm.w, suml);
            }
        }
#pragma unroll
        for (int o = 16; o; o >>= 1) suml += __shfl_xor_sync(0xffffffffu, suml, o);
        if (lane == 0) {
            float rl = g_remainL[row] / (suml + 1e-9f);
            s_rl[warp] = rl;
            g_ratioL[row] = rl;
        }
    }
    __syncthreads();
    // ---- phase 2: thread owns cols 4*tid + 1024*k (k = 0,1)
    int c4 = threadIdx.x * 4;
    float4 acc0 = make_float4(0, 0, 0, 0), acc1 = make_float4(0, 0, 0, 0);
    int ch0 = warp, ch1 = warp + 8;   // warp-uniform chunk indices
#pragma unroll 2
    for (int r = 0; r < 8; ++r) {
        const float* drow = g_d2 + ((size_t)(b * NN + row0 + r)) * MM;
        float rl = s_rl[r];
        bool a0 = __fmul_rn(kl2, s_cm[r * 16 + ch0]) > -126.0f;
        bool a1 = __fmul_rn(kl2, s_cm[r * 16 + ch1]) > -126.0f;
        float4 d40, d41;
        if (a0) d40 = *(const float4*)(drow + c4);          // loads first (MLP)
        if (a1) d41 = *(const float4*)(drow + c4 + 1024);
        if (a0) {
            acc0.x = fmaf(ex2a(__fmul_rn(kl2, d40.x)), rl, acc0.x);
            acc0.y = fmaf(ex2a(__fmul_rn(kl2, d40.y)), rl, acc0.y);
            acc0.z = fmaf(ex2a(__fmul_rn(kl2, d40.z)), rl, acc0.z);
            acc0.w = fmaf(ex2a(__fmul_rn(kl2, d40.w)), rl, acc0.w);
        }
        if (a1) {
            acc1.x = fmaf(ex2a(__fmul_rn(kl2, d41.x)), rl, acc1.x);
            acc1.y = fmaf(ex2a(__fmul_rn(kl2, d41.y)), rl, acc1.y);
            acc1.z = fmaf(ex2a(__fmul_rn(kl2, d41.z)), rl, acc1.z);
            acc1.w = fmaf(ex2a(__fmul_rn(kl2, d41.w)), rl, acc1.w);
        }
    }
    float* colA = g_colA + b * MM;
    if (acc0.x != 0.0f) atomicAdd(&colA[c4 + 0], acc0.x);
    if (acc0.y != 0.0f) atomicAdd(&colA[c4 + 1], acc0.y);
    if (acc0.z != 0.0f) atomicAdd(&colA[c4 + 2], acc0.z);
    if (acc0.w != 0.0f) atomicAdd(&colA[c4 + 3], acc0.w);
    if (acc1.x != 0.0f) atomicAdd(&colA[c4 + 1024], acc1.x);
    if (acc1.y != 0.0f) atomicAdd(&colA[c4 + 1025], acc1.y);
    if (acc1.z != 0.0f) atomicAdd(&colA[c4 + 1026], acc1.z);
    if (acc1.w != 0.0f) atomicAdd(&colA[c4 + 1027], acc1.w);
}

// --------------------------------------------------------------- kB
// ratioR inlined per-thread (bit-identical divisions); inline sqrta for
// cost; register colsums; rowsum via warp shuffle + per-warp smem atomic.
// Tail: last finishing block performs the remainR update + buffer resets
// (former kR kernel) and, on the final level, writes the output.
__global__ void __launch_bounds__(256, 5) kB(float kl2, float* out, int last) {
    __shared__ float s_rl[8];
    __shared__ float s_rowsum[8];
    __shared__ float s_cost[8];
    __shared__ float s_cm[8 * 16];
    __shared__ int s_last;
    int b = blockIdx.y;
    int row0 = blockIdx.x * 8;
    if (threadIdx.x < 128)
        s_cm[threadIdx.x] = g_cmin[(size_t)(b * NN + row0) * 16 + threadIdx.x];
    if (threadIdx.x < 8) {
        s_rl[threadIdx.x] = g_ratioL[b * NN + row0 + threadIdx.x];
        s_rowsum[threadIdx.x] = 0.0f;
    }
    __syncthreads();
    int warp = threadIdx.x >> 5, lane = threadIdx.x & 31;
    int c4 = threadIdx.x * 4;
    int ch0 = warp, ch1 = warp + 8;
    // inline ratioR for this thread's 8 columns (same operands as before)
    float4 rm0 = __ldg((const float4*)(g_remainR + b * MM + c4));
    float4 rm1 = __ldg((const float4*)(g_remainR + b * MM + c4 + 1024));
    float4 ca0 = __ldg((const float4*)(g_colA + b * MM + c4));
    float4 ca1 = __ldg((const float4*)(g_colA + b * MM + c4 + 1024));
    float4 rr0, rr1;
    rr0.x = rm0.x / (ca0.x + 1e-9f); rr0.y = rm0.y / (ca0.y + 1e-9f);
    rr0.z = rm0.z / (ca0.z + 1e-9f); rr0.w = rm0.w / (ca0.w + 1e-9f);
    rr1.x = rm1.x / (ca1.x + 1e-9f); rr1.y = rm1.y / (ca1.y + 1e-9f);
    rr1.z = rm1.z / (ca1.z + 1e-9f); rr1.w = rm1.w / (ca1.w + 1e-9f);
    float4 col0 = make_float4(0, 0, 0, 0), col1 = make_float4(0, 0, 0, 0);
    float costw = 0.0f;
#pragma unroll 2
    for (int r = 0; r < 8; ++r) {
        float rl = s_rl[r];
        const float* drow = g_d2 + ((size_t)(b * NN + row0 + r)) * MM;
        bool a0 = (rl != 0.0f) && (__fmul_rn(kl2, s_cm[r * 16 + ch0]) > -126.0f);
        bool a1 = (rl != 0.0f) && (__fmul_rn(kl2, s_cm[r * 16 + ch1]) > -126.0f);
        float4 d40, d41;
        if (a0) d40 = *(const float4*)(drow + c4);
        if (a1) d41 = *(const float4*)(drow + c4 + 1024);
        float rowpart = 0.0f;
        if (a0) {
            float w0 = __fmul_rn(__fmul_rn(ex2a(__fmul_rn(kl2, d40.x)), rl), rr0.x);
            float w1 = __fmul_rn(__fmul_rn(ex2a(__fmul_rn(kl2, d40.y)), rl), rr0.y);
            float w2 = __fmul_rn(__fmul_rn(ex2a(__fmul_rn(kl2, d40.z)), rl), rr0.z);
            float w3 = __fmul_rn(__fmul_rn(ex2a(__fmul_rn(kl2, d40.w)), rl), rr0.w);
            col0.x = __fadd_rn(col0.x, w0); col0.y = __fadd_rn(col0.y, w1);
            col0.z = __fadd_rn(col0.z, w2); col0.w = __fadd_rn(col0.w, w3);
            rowpart = __fadd_rn(rowpart, __fadd_rn(__fadd_rn(w0, w1), __fadd_rn(w2, w3)));
            costw = fmaf(w0, sqrta(fmaxf(d40.x, 1e-24f)), costw);
            costw = fmaf(w1, sqrta(fmaxf(d40.y, 1e-24f)), costw);
            costw = fmaf(w2, sqrta(fmaxf(d40.z, 1e-24f)), costw);
            costw = fmaf(w3, sqrta(fmaxf(d40.w, 1e-24f)), costw);
        }
        if (a1) {
            float w0 = __fmul_rn(__fmul_rn(ex2a(__fmul_rn(kl2, d41.x)), rl), rr1.x);
            float w1 = __fmul_rn(__fmul_rn(ex2a(__fmul_rn(kl2, d41.y)), rl), rr1.y);
            float w2 = __fmul_rn(__fmul_rn(ex2a(__fmul_rn(kl2, d41.z)), rl), rr1.z);
            float w3 = __fmul_rn(__fmul_rn(ex2a(__fmul_rn(kl2, d41.w)), rl), rr1.w);
            col1.x = __fadd_rn(col1.x, w0); col1.y = __fadd_rn(col1.y, w1);
            col1.z = __fadd_rn(col1.z, w2); col1.w = __fadd_rn(col1.w, w3);
            rowpart = __fadd_rn(rowpart, __fadd_rn(__fadd_rn(w0, w1), __fadd_rn(w2, w3)));
            costw = fmaf(w0, sqrta(fmaxf(d41.x, 1e-24f)), costw);
            costw = fmaf(w1, sqrta(fmaxf(d41.y, 1e-24f)), costw);
            costw = fmaf(w2, sqrta(fmaxf(d41.z, 1e-24f)), costw);
            costw = fmaf(w3, sqrta(fmaxf(d41.w, 1e-24f)), costw);
        }
        if (__any_sync(0xffffffffu, rowpart != 0.0f)) {
#pragma unroll
            for (int o = 16; o; o >>= 1) rowpart += __shfl_xor_sync(0xffffffffu, rowpart, o);
            if (lane == 0) atomicAdd(&s_rowsum[r], rowpart);
        }
    }
    // cost reduction
#pragma unroll
    for (int o = 16; o; o >>= 1) costw += __shfl_xor_sync(0xffffffffu, costw, o);
    if (lane == 0) s_cost[warp] = costw;
    __syncthreads();
    if (threadIdx.x < 8) {
        size_t row = (size_t)(b * NN + row0 + threadIdx.x);
        g_remainL[row] = fmaxf(__fadd_rn(g_remainL[row], -s_rowsum[threadIdx.x]), 0.0f);
    }
    if (threadIdx.x == 0) {
        float cc = 0.0f;
#pragma unroll
        for (int w = 0; w < 8; ++w) cc += s_cost[w];
        if (cc != 0.0f) atomicAdd(&g_cost[b], cc);
    }
    float* colB = g_colB + b * MM;
    if (col0.x != 0.0f) atomicAdd(&colB[c4 + 0], col0.x);
    if (col0.y != 0.0f) atomicAdd(&colB[c4 + 1], col0.y);
    if (col0.z != 0.0f) atomicAdd(&colB[c4 + 2], col0.z);
    if (col0.w != 0.0f) atomicAdd(&colB[c4 + 3], col0.w);
    if (col1.x != 0.0f) atomicAdd(&colB[c4 + 1024], col1.x);
    if (col1.y != 0.0f) atomicAdd(&colB[c4 + 1025], col1.y);
    if (col1.z != 0.0f) atomicAdd(&colB[c4 + 1026], col1.z);
    if (col1.w != 0.0f) atomicAdd(&colB[c4 + 1027], col1.w);

    // ---- last-block epilogue: former kR kernel (elementwise, deterministic)
    __threadfence();
    __syncthreads();
    if (threadIdx.x == 0)
        s_last = (atomicAdd(&g_sync, 1) == gridDim.x * gridDim.y - 1) ? 1 : 0;
    __syncthreads();
    if (s_last) {
        for (int i = threadIdx.x; i < BB * MM; i += 256) {
            g_remainR[i] = fmaxf(__fadd_rn(g_remainR[i], -g_colB[i]), 0.0f);
            g_colA[i] = 0.0f;
            g_colB[i] = 0.0f;
        }
        if (threadIdx.x == 0) {
            g_sync = 0;
            if (last)
                out[0] = (g_cost[0] + g_cost[1] + g_cost[2] + g_cost[3]) * (1.0f / (BB * NN));
        }
    }
}

// ---------------------------------------------------------------- host
extern "C" void kernel_launch(void* const* d_in, const int* in_sizes, int n_in,
                              void* d_out, int out_size) {
    const float* tm = (const float*)d_in[0];
    const float* sr = (const float*)d_in[1];

    // levels: -4^7 .. -4^-1, then 0; pre-scaled by log2(e)
    const double L2E = 1.4426950408889634;
    float kl2[10];
    double lv = -16384.0;
    for (int j = 0; j < 8; ++j) { kl2[j] = (float)(lv * L2E); lv *= 0.25; }
    kl2[8] = (float)(-0.25 * L2E);
    kl2[9] = 0.0f;

    dim3 gM(256, BB);    // 8 rows per block -> 1024 blocks
    k_d2<<<dim3(256, BB), 256>>>(tm, sr);
    for (int j = 0; j < 10; ++j) {
        kA<<<gM, 256>>>(kl2[j]);
        kB<<<gM, 256>>>(kl2[j], (float*)d_out, j == 9 ? 1 : 0);
    }
}

// round 12
// speedup vs baseline: 1.1122x; 1.1122x over previous
#include <cuda_runtime.h>
#include <math.h>

#define BB 4
#define NN 2048
#define MM 2048

// ---- persistent scratch (device globals; no allocation allowed) ----
__device__ __align__(16) float g_d2[BB * NN * MM];   // 64 MB squared distances (L2-resident)
__device__ float g_cmin[BB * NN * 16];               // per-row 128-col chunk minima
__device__ float g_remainL[BB * NN];
__device__ float g_remainR[BB * MM];
__device__ float g_ratioL[BB * NN];
__device__ float g_colA[BB * MM];   // colsum of w0*ratioL (for ratioR)
__device__ float g_colB[BB * MM];   // colsum of w (for remainR update)
__device__ float g_cost[BB];

__device__ __forceinline__ float ex2a(float x) {
    float y; asm("ex2.approx.f32 %0, %1;" : "=f"(y) : "f"(x)); return y;
}
__device__ __forceinline__ float sqrta(float x) {
    float y; asm("sqrt.approx.f32 %0, %1;" : "=f"(y) : "f"(x)); return y;
}

// ---- d2 (literal fp32 rounding) + chunk minima + state init
__global__ void k_d2(const float* __restrict__ tm, const float* __restrict__ sr) {
    __shared__ alignas(16) float sx[MM];
    __shared__ alignas(16) float sy[MM];
    __shared__ alignas(16) float sz[MM];
    int b = blockIdx.y;
    const float* sb = sr + (size_t)b * MM * 3;
    for (int i = threadIdx.x; i < MM; i += blockDim.x) {
        sx[i] = sb[3 * i]; sy[i] = sb[3 * i + 1]; sz[i] = sb[3 * i + 2];
    }
    if (blockIdx.x == 0) {       // fold k_init: one block per batch initializes state
        int bo = b * MM;
        for (int i = threadIdx.x; i < MM; i += blockDim.x) {
            g_remainL[b * NN + i] = 1.0f;   // multiL = 1 (N == M)
            g_remainR[bo + i] = 1.0f;
            g_colA[bo + i] = 0.0f;
            g_colB[bo + i] = 0.0f;
        }
        if (threadIdx.x == 0) g_cost[b] = 0.0f;
    }
    __syncthreads();
    int warp = threadIdx.x >> 5, lane = threadIdx.x & 31;
    int n = blockIdx.x * 8 + warp;
    size_t row = (size_t)(b * NN + n);
    const float* tp = tm + row * 3;
    float tx = tp[0], ty = tp[1], tz = tp[2];
    float* drow = g_d2 + row * MM;
#pragma unroll 2
    for (int it = 0; it < 16; ++it) {
        int m = it * 128 + lane * 4;
        float4 X = *(const float4*)(sx + m);
        float4 Y = *(const float4*)(sy + m);
        float4 Z = *(const float4*)(sz + m);
        float4 o;
        { float dx = __fadd_rn(tx, -X.x), dy = __fadd_rn(ty, -Y.x), dz = __fadd_rn(tz, -Z.x);
          o.x = __fadd_rn(__fadd_rn(__fmul_rn(dx, dx), __fmul_rn(dy, dy)), __fmul_rn(dz, dz)); }
        { float dx = __fadd_rn(tx, -X.y), dy = __fadd_rn(ty, -Y.y), dz = __fadd_rn(tz, -Z.y);
          o.y = __fadd_rn(__fadd_rn(__fmul_rn(dx, dx), __fmul_rn(dy, dy)), __fmul_rn(dz, dz)); }
        { float dx = __fadd_rn(tx, -X.z), dy = __fadd_rn(ty, -Y.z), dz = __fadd_rn(tz, -Z.z);
          o.z = __fadd_rn(__fadd_rn(__fmul_rn(dx, dx), __fmul_rn(dy, dy)), __fmul_rn(dz, dz)); }
        { float dx = __fadd_rn(tx, -X.w), dy = __fadd_rn(ty, -Y.w), dz = __fadd_rn(tz, -Z.w);
          o.w = __fadd_rn(__fadd_rn(__fmul_rn(dx, dx), __fmul_rn(dy, dy)), __fmul_rn(dz, dz)); }
        *(float4*)(drow + m) = o;
        float mn = fminf(fminf(o.x, o.y), fminf(o.z, o.w));
#pragma unroll
        for (int s = 16; s; s >>= 1) mn = fminf(mn, __shfl_xor_sync(0xffffffffu, mn, s));
        if (lane == 0) g_cmin[row * 16 + it] = mn;
    }
}

// --------------------------------------------------------------- kA
// 8 rows/block (grid 1024). Phase 1: compute w0, STORE to smem tile,
// suml -> ratioL (1 row/warp). Phase 2: pure-LDS column sums (no ex2,
// no global loads). Chunk skip: rn(kl2*cmin) <= -126 => ex2 flush to 0.
__global__ void __launch_bounds__(256) kA(float kl2) {   // kl2 = level*log2(e)
    extern __shared__ float s_w0[];           // 8 * 2048 floats = 64 KB dynamic
    __shared__ float s_rl[8];
    __shared__ float s_cm[8 * 16];            // cmin cache for the block's rows
    int b = blockIdx.y;
    int row0 = blockIdx.x * 8;
    if (threadIdx.x < 128)
        s_cm[threadIdx.x] = g_cmin[(size_t)(b * NN + row0) * 16 + threadIdx.x];
    __syncthreads();
    int warp = threadIdx.x >> 5, lane = threadIdx.x & 31;
    // ---- phase 1: one row per warp; w0 stored to smem
    {
        size_t row = (size_t)(b * NN + row0 + warp);
        const float* drow = g_d2 + row * MM;
        const float* rmg = g_remainR + b * MM;
        float* wrow = s_w0 + warp * MM;
        float suml = 0.0f;
#pragma unroll 2
        for (int it = 0; it < 16; ++it) {
            int m = it * 128 + lane * 4;
            if (__fmul_rn(kl2, s_cm[warp * 16 + it]) > -126.0f) {
                float4 d4 = *(const float4*)(drow + m);
                float4 rm = __ldg((const float4*)(rmg + m));
                float4 w;
                w.x = ex2a(__fmul_rn(kl2, d4.x)); w.y = ex2a(__fmul_rn(kl2, d4.y));
                w.z = ex2a(__fmul_rn(kl2, d4.z)); w.w = ex2a(__fmul_rn(kl2, d4.w));
                *(float4*)(wrow + m) = w;
                suml = fmaf(w.x, rm.x, suml); suml = fmaf(w.y, rm.y, suml);
                suml = fmaf(w.z, rm.z, suml); suml = fmaf(w.w, rm.w, suml);
            } else {
                *(float4*)(wrow + m) = make_float4(0.0f, 0.0f, 0.0f, 0.0f);
            }
        }
#pragma unroll
        for (int o = 16; o; o >>= 1) suml += __shfl_xor_sync(0xffffffffu, suml, o);
        if (lane == 0) {
            float rl = g_remainL[row] / (suml + 1e-9f);
            s_rl[warp] = rl;
            g_ratioL[row] = rl;
        }
    }
    __syncthreads();
    // ---- phase 2: thread owns cols 4*tid + 1024*k (k = 0,1); pure LDS
    int c4 = threadIdx.x * 4;
    float4 acc0 = make_float4(0, 0, 0, 0), acc1 = make_float4(0, 0, 0, 0);
    int ch0 = warp, ch1 = warp + 8;   // warp-uniform chunk indices
#pragma unroll 2
    for (int r = 0; r < 8; ++r) {
        float rl = s_rl[r];
        const float* wrow = s_w0 + r * MM;
        if (__fmul_rn(kl2, s_cm[r * 16 + ch0]) > -126.0f) {
            float4 w = *(const float4*)(wrow + c4);
            acc0.x = fmaf(w.x, rl, acc0.x); acc0.y = fmaf(w.y, rl, acc0.y);
            acc0.z = fmaf(w.z, rl, acc0.z); acc0.w = fmaf(w.w, rl, acc0.w);
        }
        if (__fmul_rn(kl2, s_cm[r * 16 + ch1]) > -126.0f) {
            float4 w = *(const float4*)(wrow + c4 + 1024);
            acc1.x = fmaf(w.x, rl, acc1.x); acc1.y = fmaf(w.y, rl, acc1.y);
            acc1.z = fmaf(w.z, rl, acc1.z); acc1.w = fmaf(w.w, rl, acc1.w);
        }
    }
    float* colA = g_colA + b * MM;
    if (acc0.x != 0.0f) atomicAdd(&colA[c4 + 0], acc0.x);
    if (acc0.y != 0.0f) atomicAdd(&colA[c4 + 1], acc0.y);
    if (acc0.z != 0.0f) atomicAdd(&colA[c4 + 2], acc0.z);
    if (acc0.w != 0.0f) atomicAdd(&colA[c4 + 3], acc0.w);
    if (acc1.x != 0.0f) atomicAdd(&colA[c4 + 1024], acc1.x);
    if (acc1.y != 0.0f) atomicAdd(&colA[c4 + 1025], acc1.y);
    if (acc1.z != 0.0f) atomicAdd(&colA[c4 + 1026], acc1.z);
    if (acc1.w != 0.0f) atomicAdd(&colA[c4 + 1027], acc1.w);
}

// --------------------------------------------------------------- kB
// ratioR inlined per-thread (bit-identical divisions); inline sqrta for
// cost; register colsums; rowsum via warp shuffle + per-warp smem atomic.
__global__ void __launch_bounds__(256, 5) kB(float kl2) {
    __shared__ float s_rl[8];
    __shared__ float s_rowsum[8];
    __shared__ float s_cost[8];
    __shared__ float s_cm[8 * 16];
    int b = blockIdx.y;
    int row0 = blockIdx.x * 8;
    if (threadIdx.x < 128)
        s_cm[threadIdx.x] = g_cmin[(size_t)(b * NN + row0) * 16 + threadIdx.x];
    if (threadIdx.x < 8) {
        s_rl[threadIdx.x] = g_ratioL[b * NN + row0 + threadIdx.x];
        s_rowsum[threadIdx.x] = 0.0f;
    }
    __syncthreads();
    int warp = threadIdx.x >> 5, lane = threadIdx.x & 31;
    int c4 = threadIdx.x * 4;
    int ch0 = warp, ch1 = warp + 8;
    // inline ratioR for this thread's 8 columns (same operands -> bit-identical)
    float4 rm0 = __ldg((const float4*)(g_remainR + b * MM + c4));
    float4 rm1 = __ldg((const float4*)(g_remainR + b * MM + c4 + 1024));
    float4 ca0 = __ldg((const float4*)(g_colA + b * MM + c4));
    float4 ca1 = __ldg((const float4*)(g_colA + b * MM + c4 + 1024));
    float4 rr0, rr1;
    rr0.x = rm0.x / (ca0.x + 1e-9f); rr0.y = rm0.y / (ca0.y + 1e-9f);
    rr0.z = rm0.z / (ca0.z + 1e-9f); rr0.w = rm0.w / (ca0.w + 1e-9f);
    rr1.x = rm1.x / (ca1.x + 1e-9f); rr1.y = rm1.y / (ca1.y + 1e-9f);
    rr1.z = rm1.z / (ca1.z + 1e-9f); rr1.w = rm1.w / (ca1.w + 1e-9f);
    float4 col0 = make_float4(0, 0, 0, 0), col1 = make_float4(0, 0, 0, 0);
    float costw = 0.0f;
#pragma unroll 2
    for (int r = 0; r < 8; ++r) {
        float rl = s_rl[r];
        const float* drow = g_d2 + ((size_t)(b * NN + row0 + r)) * MM;
        bool a0 = (rl != 0.0f) && (__fmul_rn(kl2, s_cm[r * 16 + ch0]) > -126.0f);
        bool a1 = (rl != 0.0f) && (__fmul_rn(kl2, s_cm[r * 16 + ch1]) > -126.0f);
        float4 d40, d41;
        if (a0) d40 = *(const float4*)(drow + c4);
        if (a1) d41 = *(const float4*)(drow + c4 + 1024);
        float rowpart = 0.0f;
        if (a0) {
            float w0 = __fmul_rn(__fmul_rn(ex2a(__fmul_rn(kl2, d40.x)), rl), rr0.x);
            float w1 = __fmul_rn(__fmul_rn(ex2a(__fmul_rn(kl2, d40.y)), rl), rr0.y);
            float w2 = __fmul_rn(__fmul_rn(ex2a(__fmul_rn(kl2, d40.z)), rl), rr0.z);
            float w3 = __fmul_rn(__fmul_rn(ex2a(__fmul_rn(kl2, d40.w)), rl), rr0.w);
            col0.x = __fadd_rn(col0.x, w0); col0.y = __fadd_rn(col0.y, w1);
            col0.z = __fadd_rn(col0.z, w2); col0.w = __fadd_rn(col0.w, w3);
            rowpart = __fadd_rn(rowpart, __fadd_rn(__fadd_rn(w0, w1), __fadd_rn(w2, w3)));
            costw = fmaf(w0, sqrta(fmaxf(d40.x, 1e-24f)), costw);
            costw = fmaf(w1, sqrta(fmaxf(d40.y, 1e-24f)), costw);
            costw = fmaf(w2, sqrta(fmaxf(d40.z, 1e-24f)), costw);
            costw = fmaf(w3, sqrta(fmaxf(d40.w, 1e-24f)), costw);
        }
        if (a1) {
            float w0 = __fmul_rn(__fmul_rn(ex2a(__fmul_rn(kl2, d41.x)), rl), rr1.x);
            float w1 = __fmul_rn(__fmul_rn(ex2a(__fmul_rn(kl2, d41.y)), rl), rr1.y);
            float w2 = __fmul_rn(__fmul_rn(ex2a(__fmul_rn(kl2, d41.z)), rl), rr1.z);
            float w3 = __fmul_rn(__fmul_rn(ex2a(__fmul_rn(kl2, d41.w)), rl), rr1.w);
            col1.x = __fadd_rn(col1.x, w0); col1.y = __fadd_rn(col1.y, w1);
            col1.z = __fadd_rn(col1.z, w2); col1.w = __fadd_rn(col1.w, w3);
            rowpart = __fadd_rn(rowpart, __fadd_rn(__fadd_rn(w0, w1), __fadd_rn(w2, w3)));
            costw = fmaf(w0, sqrta(fmaxf(d41.x, 1e-24f)), costw);
            costw = fmaf(w1, sqrta(fmaxf(d41.y, 1e-24f)), costw);
            costw = fmaf(w2, sqrta(fmaxf(d41.z, 1e-24f)), costw);
            costw = fmaf(w3, sqrta(fmaxf(d41.w, 1e-24f)), costw);
        }
        if (__any_sync(0xffffffffu, rowpart != 0.0f)) {
#pragma unroll
            for (int o = 16; o; o >>= 1) rowpart += __shfl_xor_sync(0xffffffffu, rowpart, o);
            if (lane == 0) atomicAdd(&s_rowsum[r], rowpart);
        }
    }
    // cost reduction
#pragma unroll
    for (int o = 16; o; o >>= 1) costw += __shfl_xor_sync(0xffffffffu, costw, o);
    if (lane == 0) s_cost[warp] = costw;
    __syncthreads();
    if (threadIdx.x < 8) {
        size_t row = (size_t)(b * NN + row0 + threadIdx.x);
        g_remainL[row] = fmaxf(__fadd_rn(g_remainL[row], -s_rowsum[threadIdx.x]), 0.0f);
    }
    if (threadIdx.x == 0) {
        float cc = 0.0f;
#pragma unroll
        for (int w = 0; w < 8; ++w) cc += s_cost[w];
        if (cc != 0.0f) atomicAdd(&g_cost[b], cc);
    }
    float* colB = g_colB + b * MM;
    if (col0.x != 0.0f) atomicAdd(&colB[c4 + 0], col0.x);
    if (col0.y != 0.0f) atomicAdd(&colB[c4 + 1], col0.y);
    if (col0.z != 0.0f) atomicAdd(&colB[c4 + 2], col0.z);
    if (col0.w != 0.0f) atomicAdd(&colB[c4 + 3], col0.w);
    if (col1.x != 0.0f) atomicAdd(&colB[c4 + 1024], col1.x);
    if (col1.y != 0.0f) atomicAdd(&colB[c4 + 1025], col1.y);
    if (col1.z != 0.0f) atomicAdd(&colB[c4 + 1026], col1.z);
    if (col1.w != 0.0f) atomicAdd(&colB[c4 + 1027], col1.w);
}

// --- remainR = max(remainR - colB, 0); reset cols; last: write output
__global__ void kR(float* out, int last) {
    int i = blockIdx.x * blockDim.x + threadIdx.x;
    if (i < BB * MM) {
        g_remainR[i] = fmaxf(__fadd_rn(g_remainR[i], -g_colB[i]), 0.0f);
        g_colA[i] = 0.0f;
        g_colB[i] = 0.0f;
    }
    if (last && i == 0)
        out[0] = (g_cost[0] + g_cost[1] + g_cost[2] + g_cost[3]) * (1.0f / (BB * NN));
}

// ---------------------------------------------------------------- host
extern "C" void kernel_launch(void* const* d_in, const int* in_sizes, int n_in,
                              void* d_out, int out_size) {
    const float* tm = (const float*)d_in[0];
    const float* sr = (const float*)d_in[1];

    // levels: -4^7 .. -4^-1, then 0; pre-scaled by log2(e)
    const double L2E = 1.4426950408889634;
    float kl2[10];
    double lv = -16384.0;
    for (int j = 0; j < 8; ++j) { kl2[j] = (float)(lv * L2E); lv *= 0.25; }
    kl2[8] = (float)(-0.25 * L2E);
    kl2[9] = 0.0f;

    const int W0_SMEM = 8 * MM * (int)sizeof(float);   // 64 KB dynamic
    static int attr_done = 0;
    if (!attr_done) {
        cudaFuncSetAttribute(kA, cudaFuncAttributeMaxDynamicSharedMemorySize, W0_SMEM);
        attr_done = 1;
    }

    dim3 gM(256, BB);    // 8 rows per block -> 1024 blocks
    k_d2<<<dim3(256, BB), 256>>>(tm, sr);
    for (int j = 0; j < 10; ++j) {
        kA<<<gM, 256, W0_SMEM>>>(kl2[j]);
        kB<<<gM, 256>>>(kl2[j]);
        kR<<<16, 512>>>((float*)d_out, j == 9 ? 1 : 0);
    }
}

// round 13
// speedup vs baseline: 1.3321x; 1.1978x over previous
#include <cuda_runtime.h>
#include <math.h>

#define BB 4
#define NN 2048
#define MM 2048

// ---- persistent scratch (device globals; no allocation allowed) ----
__device__ __align__(16) float g_d2[BB * NN * MM];   // 64 MB squared distances (L2-resident)
__device__ float g_cmin[BB * NN * 16];               // per-row 128-col chunk minima
__device__ float g_remainL[BB * NN];
__device__ float g_remainR[BB * MM];   // value AFTER previous level's update (kC persists)
__device__ float g_ratioL[BB * NN];
__device__ float g_ratioR[BB * MM];
__device__ float g_colA[BB * MM];   // colsum of w0*ratioL (consumed+reset by kC)
__device__ float g_colB[BB * MM];   // colsum of w (consumed by next kA/kC; reset by kC)
__device__ float g_cost[BB];

__device__ __forceinline__ float ex2a(float x) {
    float y; asm("ex2.approx.f32 %0, %1;" : "=f"(y) : "f"(x)); return y;
}
__device__ __forceinline__ float sqrta(float x) {
    float y; asm("sqrt.approx.f32 %0, %1;" : "=f"(y) : "f"(x)); return y;
}

// ---- d2 (literal fp32 rounding) + chunk minima + state init
__global__ void k_d2(const float* __restrict__ tm, const float* __restrict__ sr) {
    __shared__ alignas(16) float sx[MM];
    __shared__ alignas(16) float sy[MM];
    __shared__ alignas(16) float sz[MM];
    int b = blockIdx.y;
    const float* sb = sr + (size_t)b * MM * 3;
    for (int i = threadIdx.x; i < MM; i += blockDim.x) {
        sx[i] = sb[3 * i]; sy[i] = sb[3 * i + 1]; sz[i] = sb[3 * i + 2];
    }
    if (blockIdx.x == 0) {       // fold k_init: one block per batch initializes state
        int bo = b * MM;
        for (int i = threadIdx.x; i < MM; i += blockDim.x) {
            g_remainL[b * NN + i] = 1.0f;   // multiL = 1 (N == M)
            g_remainR[bo + i] = 1.0f;
            g_colA[bo + i] = 0.0f;
            g_colB[bo + i] = 0.0f;
        }
        if (threadIdx.x == 0) g_cost[b] = 0.0f;
    }
    __syncthreads();
    int warp = threadIdx.x >> 5, lane = threadIdx.x & 31;
    int n = blockIdx.x * 8 + warp;
    size_t row = (size_t)(b * NN + n);
    const float* tp = tm + row * 3;
    float tx = tp[0], ty = tp[1], tz = tp[2];
    float* drow = g_d2 + row * MM;
#pragma unroll 2
    for (int it = 0; it < 16; ++it) {
        int m = it * 128 + lane * 4;
        float4 X = *(const float4*)(sx + m);
        float4 Y = *(const float4*)(sy + m);
        float4 Z = *(const float4*)(sz + m);
        float4 o;
        { float dx = __fadd_rn(tx, -X.x), dy = __fadd_rn(ty, -Y.x), dz = __fadd_rn(tz, -Z.x);
          o.x = __fadd_rn(__fadd_rn(__fmul_rn(dx, dx), __fmul_rn(dy, dy)), __fmul_rn(dz, dz)); }
        { float dx = __fadd_rn(tx, -X.y), dy = __fadd_rn(ty, -Y.y), dz = __fadd_rn(tz, -Z.y);
          o.y = __fadd_rn(__fadd_rn(__fmul_rn(dx, dx), __fmul_rn(dy, dy)), __fmul_rn(dz, dz)); }
        { float dx = __fadd_rn(tx, -X.z), dy = __fadd_rn(ty, -Y.z), dz = __fadd_rn(tz, -Z.z);
          o.z = __fadd_rn(__fadd_rn(__fmul_rn(dx, dx), __fmul_rn(dy, dy)), __fmul_rn(dz, dz)); }
        { float dx = __fadd_rn(tx, -X.w), dy = __fadd_rn(ty, -Y.w), dz = __fadd_rn(tz, -Z.w);
          o.w = __fadd_rn(__fadd_rn(__fmul_rn(dx, dx), __fmul_rn(dy, dy)), __fmul_rn(dz, dz)); }
        *(float4*)(drow + m) = o;
        float mn = fminf(fminf(o.x, o.y), fminf(o.z, o.w));
#pragma unroll
        for (int s = 16; s; s >>= 1) mn = fminf(mn, __shfl_xor_sync(0xffffffffu, mn, s));
        if (lane == 0) g_cmin[row * 16 + it] = mn;
    }
}

// --------------------------------------------------------------- kA
// 8 rows/block (grid 1024). Phase 1: suml -> ratioL (1 row/warp), with
// remainR updated ON THE FLY: rm_eff = max(remainR - colB_prev, 0)
// (bit-identical to the old kR's expression). Phase 2 (column-ownership,
// float4): colA[c] += sum_rows w0*ratioL.
// Chunk skip: rn(kl2*cmin) <= -126 (log2 units) => all 128 ex2 flush to 0.
__global__ void __launch_bounds__(256, 5) kA(float kl2) {   // kl2 = level*log2(e)
    __shared__ float s_rl[8];
    __shared__ float s_cm[8 * 16];            // cmin cache for the block's rows
    int b = blockIdx.y;
    int row0 = blockIdx.x * 8;
    if (threadIdx.x < 128)
        s_cm[threadIdx.x] = g_cmin[(size_t)(b * NN + row0) * 16 + threadIdx.x];
    __syncthreads();
    int warp = threadIdx.x >> 5, lane = threadIdx.x & 31;
    // ---- phase 1: one row per warp
    {
        size_t row = (size_t)(b * NN + row0 + warp);
        const float* drow = g_d2 + row * MM;
        const float* rmg = g_remainR + b * MM;
        const float* cbg = g_colB + b * MM;
        float suml = 0.0f;
#pragma unroll 2
        for (int it = 0; it < 16; ++it) {
            if (__fmul_rn(kl2, s_cm[warp * 16 + it]) > -126.0f) {
                int m = it * 128 + lane * 4;
                float4 d4 = *(const float4*)(drow + m);
                float4 rm = __ldg((const float4*)(rmg + m));
                float4 cb = __ldg((const float4*)(cbg + m));
                rm.x = fmaxf(__fadd_rn(rm.x, -cb.x), 0.0f);
                rm.y = fmaxf(__fadd_rn(rm.y, -cb.y), 0.0f);
                rm.z = fmaxf(__fadd_rn(rm.z, -cb.z), 0.0f);
                rm.w = fmaxf(__fadd_rn(rm.w, -cb.w), 0.0f);
                suml = fmaf(ex2a(__fmul_rn(kl2, d4.x)), rm.x, suml);
                suml = fmaf(ex2a(__fmul_rn(kl2, d4.y)), rm.y, suml);
                suml = fmaf(ex2a(__fmul_rn(kl2, d4.z)), rm.z, suml);
                suml = fmaf(ex2a(__fmul_rn(kl2, d4.w)), rm.w, suml);
            }
        }
#pragma unroll
        for (int o = 16; o; o >>= 1) suml += __shfl_xor_sync(0xffffffffu, suml, o);
        if (lane == 0) {
            float rl = g_remainL[row] / (suml + 1e-9f);
            s_rl[warp] = rl;
            g_ratioL[row] = rl;
        }
    }
    __syncthreads();
    // ---- phase 2: thread owns cols 4*tid + 1024*k (k = 0,1)
    int c4 = threadIdx.x * 4;
    float4 acc0 = make_float4(0, 0, 0, 0), acc1 = make_float4(0, 0, 0, 0);
    int ch0 = warp, ch1 = warp + 8;   // warp-uniform chunk indices
#pragma unroll 2
    for (int r = 0; r < 8; ++r) {
        const float* drow = g_d2 + ((size_t)(b * NN + row0 + r)) * MM;
        float rl = s_rl[r];
        bool a0 = __fmul_rn(kl2, s_cm[r * 16 + ch0]) > -126.0f;
        bool a1 = __fmul_rn(kl2, s_cm[r * 16 + ch1]) > -126.0f;
        float4 d40, d41;
        if (a0) d40 = *(const float4*)(drow + c4);          // loads first (MLP)
        if (a1) d41 = *(const float4*)(drow + c4 + 1024);
        if (a0) {
            acc0.x = fmaf(ex2a(__fmul_rn(kl2, d40.x)), rl, acc0.x);
            acc0.y = fmaf(ex2a(__fmul_rn(kl2, d40.y)), rl, acc0.y);
            acc0.z = fmaf(ex2a(__fmul_rn(kl2, d40.z)), rl, acc0.z);
            acc0.w = fmaf(ex2a(__fmul_rn(kl2, d40.w)), rl, acc0.w);
        }
        if (a1) {
            acc1.x = fmaf(ex2a(__fmul_rn(kl2, d41.x)), rl, acc1.x);
            acc1.y = fmaf(ex2a(__fmul_rn(kl2, d41.y)), rl, acc1.y);
            acc1.z = fmaf(ex2a(__fmul_rn(kl2, d41.z)), rl, acc1.z);
            acc1.w = fmaf(ex2a(__fmul_rn(kl2, d41.w)), rl, acc1.w);
        }
    }
    float* colA = g_colA + b * MM;
    if (acc0.x != 0.0f) atomicAdd(&colA[c4 + 0], acc0.x);
    if (acc0.y != 0.0f) atomicAdd(&colA[c4 + 1], acc0.y);
    if (acc0.z != 0.0f) atomicAdd(&colA[c4 + 2], acc0.z);
    if (acc0.w != 0.0f) atomicAdd(&colA[c4 + 3], acc0.w);
    if (acc1.x != 0.0f) atomicAdd(&colA[c4 + 1024], acc1.x);
    if (acc1.y != 0.0f) atomicAdd(&colA[c4 + 1025], acc1.y);
    if (acc1.z != 0.0f) atomicAdd(&colA[c4 + 1026], acc1.z);
    if (acc1.w != 0.0f) atomicAdd(&colA[c4 + 1027], acc1.w);
}

// ---- kC: single writer. Persist remainR (same expression as kA's
// on-the-fly update -> bit-identical), ratioR = remainR/(colA+1e-9),
// reset colA and colB for the next accumulation.
__global__ void kC() {
    int i = blockIdx.x * blockDim.x + threadIdx.x;
    if (i >= BB * MM) return;
    float rm = fmaxf(__fadd_rn(g_remainR[i], -g_colB[i]), 0.0f);
    g_remainR[i] = rm;
    g_ratioR[i] = rm / (g_colA[i] + 1e-9f);
    g_colA[i] = 0.0f;
    g_colB[i] = 0.0f;
}

// --------------------------------------------------------------- kB
// ratioR from kC (two float4 ldg); w = (w0*ratioL)*ratioR; register
// colsums; rowsum via warp shuffle + per-warp smem atomic; cost in regs.
__global__ void __launch_bounds__(256, 5) kB(float kl2) {
    __shared__ float s_rl[8];
    __shared__ float s_rowsum[8];
    __shared__ float s_cost[8];
    __shared__ float s_cm[8 * 16];
    int b = blockIdx.y;
    int row0 = blockIdx.x * 8;
    if (threadIdx.x < 128)
        s_cm[threadIdx.x] = g_cmin[(size_t)(b * NN + row0) * 16 + threadIdx.x];
    if (threadIdx.x < 8) {
        s_rl[threadIdx.x] = g_ratioL[b * NN + row0 + threadIdx.x];
        s_rowsum[threadIdx.x] = 0.0f;
    }
    __syncthreads();
    int warp = threadIdx.x >> 5, lane = threadIdx.x & 31;
    int c4 = threadIdx.x * 4;
    int ch0 = warp, ch1 = warp + 8;
    float4 rr0 = __ldg((const float4*)(g_ratioR + b * MM + c4));
    float4 rr1 = __ldg((const float4*)(g_ratioR + b * MM + c4 + 1024));
    float4 col0 = make_float4(0, 0, 0, 0), col1 = make_float4(0, 0, 0, 0);
    float costw = 0.0f;
#pragma unroll 2
    for (int r = 0; r < 8; ++r) {
        float rl = s_rl[r];
        const float* drow = g_d2 + ((size_t)(b * NN + row0 + r)) * MM;
        bool a0 = (rl != 0.0f) && (__fmul_rn(kl2, s_cm[r * 16 + ch0]) > -126.0f);
        bool a1 = (rl != 0.0f) && (__fmul_rn(kl2, s_cm[r * 16 + ch1]) > -126.0f);
        float4 d40, d41;
        if (a0) d40 = *(const float4*)(drow + c4);
        if (a1) d41 = *(const float4*)(drow + c4 + 1024);
        float rowpart = 0.0f;
        if (a0) {
            float w0 = __fmul_rn(__fmul_rn(ex2a(__fmul_rn(kl2, d40.x)), rl), rr0.x);
            float w1 = __fmul_rn(__fmul_rn(ex2a(__fmul_rn(kl2, d40.y)), rl), rr0.y);
            float w2 = __fmul_rn(__fmul_rn(ex2a(__fmul_rn(kl2, d40.z)), rl), rr0.z);
            float w3 = __fmul_rn(__fmul_rn(ex2a(__fmul_rn(kl2, d40.w)), rl), rr0.w);
            col0.x = __fadd_rn(col0.x, w0); col0.y = __fadd_rn(col0.y, w1);
            col0.z = __fadd_rn(col0.z, w2); col0.w = __fadd_rn(col0.w, w3);
            rowpart = __fadd_rn(rowpart, __fadd_rn(__fadd_rn(w0, w1), __fadd_rn(w2, w3)));
            costw = fmaf(w0, sqrta(fmaxf(d40.x, 1e-24f)), costw);
            costw = fmaf(w1, sqrta(fmaxf(d40.y, 1e-24f)), costw);
            costw = fmaf(w2, sqrta(fmaxf(d40.z, 1e-24f)), costw);
            costw = fmaf(w3, sqrta(fmaxf(d40.w, 1e-24f)), costw);
        }
        if (a1) {
            float w0 = __fmul_rn(__fmul_rn(ex2a(__fmul_rn(kl2, d41.x)), rl), rr1.x);
            float w1 = __fmul_rn(__fmul_rn(ex2a(__fmul_rn(kl2, d41.y)), rl), rr1.y);
            float w2 = __fmul_rn(__fmul_rn(ex2a(__fmul_rn(kl2, d41.z)), rl), rr1.z);
            float w3 = __fmul_rn(__fmul_rn(ex2a(__fmul_rn(kl2, d41.w)), rl), rr1.w);
            col1.x = __fadd_rn(col1.x, w0); col1.y = __fadd_rn(col1.y, w1);
            col1.z = __fadd_rn(col1.z, w2); col1.w = __fadd_rn(col1.w, w3);
            rowpart = __fadd_rn(rowpart, __fadd_rn(__fadd_rn(w0, w1), __fadd_rn(w2, w3)));
            costw = fmaf(w0, sqrta(fmaxf(d41.x, 1e-24f)), costw);
            costw = fmaf(w1, sqrta(fmaxf(d41.y, 1e-24f)), costw);
            costw = fmaf(w2, sqrta(fmaxf(d41.z, 1e-24f)), costw);
            costw = fmaf(w3, sqrta(fmaxf(d41.w, 1e-24f)), costw);
        }
        if (__any_sync(0xffffffffu, rowpart != 0.0f)) {
#pragma unroll
            for (int o = 16; o; o >>= 1) rowpart += __shfl_xor_sync(0xffffffffu, rowpart, o);
            if (lane == 0) atomicAdd(&s_rowsum[r], rowpart);
        }
    }
    // cost reduction
#pragma unroll
    for (int o = 16; o; o >>= 1) costw += __shfl_xor_sync(0xffffffffu, costw, o);
    if (lane == 0) s_cost[warp] = costw;
    __syncthreads();
    if (threadIdx.x < 8) {
        size_t row = (size_t)(b * NN + row0 + threadIdx.x);
        g_remainL[row] = fmaxf(__fadd_rn(g_remainL[row], -s_rowsum[threadIdx.x]), 0.0f);
    }
    if (threadIdx.x == 0) {
        float cc = 0.0f;
#pragma unroll
        for (int w = 0; w < 8; ++w) cc += s_cost[w];
        if (cc != 0.0f) atomicAdd(&g_cost[b], cc);
    }
    float* colB = g_colB + b * MM;
    if (col0.x != 0.0f) atomicAdd(&colB[c4 + 0], col0.x);
    if (col0.y != 0.0f) atomicAdd(&colB[c4 + 1], col0.y);
    if (col0.z != 0.0f) atomicAdd(&colB[c4 + 2], col0.z);
    if (col0.w != 0.0f) atomicAdd(&colB[c4 + 3], col0.w);
    if (col1.x != 0.0f) atomicAdd(&colB[c4 + 1024], col1.x);
    if (col1.y != 0.0f) atomicAdd(&colB[c4 + 1025], col1.y);
    if (col1.z != 0.0f) atomicAdd(&colB[c4 + 1026], col1.z);
    if (col1.w != 0.0f) atomicAdd(&colB[c4 + 1027], col1.w);
}

// ---------------------------------------------------------- output
__global__ void k_out(float* out) {
    out[0] = (g_cost[0] + g_cost[1] + g_cost[2] + g_cost[3]) * (1.0f / (BB * NN));
}

// ---------------------------------------------------------------- host
extern "C" void kernel_launch(void* const* d_in, const int* in_sizes, int n_in,
                              void* d_out, int out_size) {
    const float* tm = (const float*)d_in[0];
    const float* sr = (const float*)d_in[1];

    // levels: -4^7 .. -4^-1, then 0; pre-scaled by log2(e)
    const double L2E = 1.4426950408889634;
    float kl2[10];
    double lv = -16384.0;
    for (int j = 0; j < 8; ++j) { kl2[j] = (float)(lv * L2E); lv *= 0.25; }
    kl2[8] = (float)(-0.25 * L2E);
    kl2[9] = 0.0f;

    dim3 gM(256, BB);    // 8 rows per block -> 1024 blocks
    k_d2<<<dim3(256, BB), 256>>>(tm, sr);
    for (int j = 0; j < 10; ++j) {
        kA<<<gM, 256>>>(kl2[j]);
        kC<<<16, 512>>>();
        kB<<<gM, 256>>>(kl2[j]);
    }
    k_out<<<1, 1>>>((float*)d_out);
}